// round 4
// baseline (speedup 1.0000x reference)
#include <cuda_runtime.h>

#define DEV_INLINE __device__ __forceinline__

constexpr int cN   = 100000;   // nodes
constexpr int cE   = 1600000;  // edges
constexpr int cDIN = 32;       // node in channels
constexpr int cDE  = 16;       // edge feature dim
constexpr int cH   = 64;       // hidden
constexpr int cMH  = 128;      // mlp hidden
constexpr int cOUT = 10;       // out channels
constexpr int cG   = 128;      // graphs

typedef unsigned long long ull;

// ---------------- scratch (device globals; no allocation allowed) ----------
__device__ __align__(16) float g_u[cN * cH];       // x + agg (node MLP input)
__device__ __align__(16) float g_h[cN * cH];       // node MLP output (pre-BN)
__device__ __align__(16) float g_x[cN * cH];       // post-BN activations
__device__ __align__(16) float g_ea_perm[(size_t)cE * cDE];  // ea in CSR order
__device__ __align__(16) int   g_src[cE];          // src in CSR order
__device__ __align__(16) int   g_deg[cN];
__device__ __align__(16) int   g_woff[cN];
__device__ __align__(16) int   g_rowptr[cN + 1];
__device__ __align__(16) float g_sum[cH];
__device__ __align__(16) float g_sumsq[cH];
__device__ __align__(16) float g_pool[cG * cH];
__device__ __align__(16) int   g_cnt[cG];

DEV_INLINE void red_add_v4(float* p, float a, float b, float c, float d) {
    asm volatile("red.global.add.v4.f32 [%0], {%1,%2,%3,%4};"
                 :: "l"(p), "f"(a), "f"(b), "f"(c), "f"(d) : "memory");
}
DEV_INLINE ull ffma2(ull a, ull b, ull c) {
    ull d;
    asm("fma.rn.f32x2 %0, %1, %2, %3;" : "=l"(d) : "l"(a), "l"(b), "l"(c));
    return d;
}
DEV_INLINE ull pack2(float lo, float hi) {
    ull v;
    asm("mov.b64 %0, {%1, %2};" : "=l"(v) : "f"(lo), "f"(hi));
    return v;
}
DEV_INLINE float2 unpack2(ull v) {
    float2 f;
    asm("mov.b64 {%0, %1}, %2;" : "=f"(f.x), "=f"(f.y) : "l"(v));
    return f;
}

// ---------------- init + CSR build -----------------------------------------
__global__ void __launch_bounds__(256) init_kernel() {
    int i = blockIdx.x * 256 + threadIdx.x;
    if (i < cN) g_deg[i] = 0;
    if (i < cG * cH) g_pool[i] = 0.f;
    if (i < cG) g_cnt[i] = 0;
    if (i < cH) { g_sum[i] = 0.f; g_sumsq[i] = 0.f; }
}

__global__ void __launch_bounds__(256) hist_kernel(const int* __restrict__ ei) {
    int e = blockIdx.x * 256 + threadIdx.x;
    if (e < cE) atomicAdd(&g_deg[ei[cE + e]], 1);
}

__global__ void __launch_bounds__(1024) scan_kernel() {
    const int TP = (cN + 1023) / 1024;  // 98
    int t = threadIdx.x;
    int s0 = t * TP, s1 = min(s0 + TP, cN);
    int ls = 0;
    for (int i = s0; i < s1; i++) ls += g_deg[i];
    __shared__ int ps[1024];
    ps[t] = ls;
    __syncthreads();
    for (int off = 1; off < 1024; off <<= 1) {
        int v = (t >= off) ? ps[t - off] : 0;
        __syncthreads();
        ps[t] += v;
        __syncthreads();
    }
    int run = ps[t] - ls;
    for (int i = s0; i < s1; i++) {
        g_rowptr[i] = run;
        g_woff[i]   = run;
        run += g_deg[i];
    }
    if (t == 0) g_rowptr[cN] = cE;
}

// scatter + permute edge_attr into CSR (dst-sorted) order, fused
__global__ void __launch_bounds__(256) scatter_kernel(
    const int* __restrict__ ei, const float* __restrict__ ea)
{
    int e = blockIdx.x * 256 + threadIdx.x;
    if (e >= cE) return;
    int s = ei[e], d = ei[cE + e];
    int pos = atomicAdd(&g_woff[d], 1);
    g_src[pos] = s;
    const float4* sp = (const float4*)(ea + (size_t)e * cDE);
    float4 a = sp[0], b = sp[1], c = sp[2], dd = sp[3];
    float4* dp = (float4*)(g_ea_perm + (size_t)pos * cDE);
    dp[0] = a; dp[1] = b; dp[2] = c; dp[3] = dd;
}

// ---------------- edge message + gather aggregate --------------------------
// u[d] = x[d] + sum_{e in CSR[d]} relu(x[src_e] + ea_e @ ew^T + eb)
// Warp per node (32 lanes, CPT = C/32 channels each). Edge data staged to
// smem coalesced per 8-node block; weights in registers (f32x2 pairs).
// Edge loop unrolled x4 with batched x[src] loads (MLP=4) to beat L2 latency.
template <int C>
__global__ void __launch_bounds__(256) gather_kernel(
    const float* __restrict__ xin, int use_internal,
    const float* __restrict__ ew, const float* __restrict__ eb)
{
    constexpr int CPT   = C / 32;   // 1 (layer0) or 2
    constexpr int KP    = cDE / 2;  // 8 k-pairs
    constexpr int CHUNK = 256;

    __shared__ __align__(16) float ea_s[CHUNK * cDE];
    __shared__ int src_s[CHUNK];

    const float* x = use_internal ? g_x : xin;
    int t = threadIdx.x;

    if (blockIdx.x == 0 && t < cH) { g_sum[t] = 0.f; g_sumsq[t] = 0.f; }

    int lane = t & 31;
    int c0 = lane * CPT;

    ull wreg[CPT][KP];
    float ebr[CPT];
    #pragma unroll
    for (int c = 0; c < CPT; c++) {
        #pragma unroll
        for (int j = 0; j < KP; j++)
            wreg[c][j] = *(const ull*)&ew[(c0 + c) * cDE + 2 * j];
        ebr[c] = eb[c0 + c];
    }

    int n0 = blockIdx.x * 8;
    int node = n0 + (t >> 5);
    int es_blk = g_rowptr[n0], ee_blk = g_rowptr[n0 + 8];
    int es = g_rowptr[node], ee = g_rowptr[node + 1];

    float acc[CPT];
    #pragma unroll
    for (int c = 0; c < CPT; c++) acc[c] = 0.f;

    for (int base = es_blk; base < ee_blk; base += CHUNK) {
        int cnt = min(CHUNK, ee_blk - base);
        __syncthreads();
        for (int i = t; i < cnt * (cDE / 4); i += 256)
            ((float4*)ea_s)[i] = ((const float4*)g_ea_perm)[(size_t)base * 4 + i];
        for (int i = t; i < cnt; i += 256) src_s[i] = g_src[base + i];
        __syncthreads();

        int e0 = max(es, base), e1 = min(ee, base + cnt);
        int e = e0;

        // main loop: 4 edges per iteration, loads batched up front
        for (; e + 4 <= e1; e += 4) {
            int i0 = e - base;
            int ss[4];
            #pragma unroll
            for (int r = 0; r < 4; r++) ss[r] = src_s[i0 + r];
            float xa[4], xb[4];
            if (CPT == 2) {
                #pragma unroll
                for (int r = 0; r < 4; r++) {
                    float2 xx = *(const float2*)(x + (size_t)ss[r] * C + c0);
                    xa[r] = xx.x; xb[r] = xx.y;
                }
            } else {
                #pragma unroll
                for (int r = 0; r < 4; r++) xa[r] = x[(size_t)ss[r] * C + c0];
            }
            #pragma unroll
            for (int r = 0; r < 4; r++) {
                const ull* eap = (const ull*)&ea_s[(i0 + r) * cDE];
                #pragma unroll
                for (int c = 0; c < CPT; c++) {
                    ull d2 = pack2(ebr[c], 0.f);
                    #pragma unroll
                    for (int j = 0; j < KP; j++) d2 = ffma2(wreg[c][j], eap[j], d2);
                    float2 p = unpack2(d2);
                    float xv = (c == 0) ? xa[r] : xb[r];
                    acc[c] += fmaxf(xv + p.x + p.y, 0.f);
                }
            }
        }
        // remainder
        for (; e < e1; e++) {
            int idx = e - base;
            int s = src_s[idx];
            const ull* eap = (const ull*)&ea_s[idx * cDE];
            float xv[CPT];
            if (CPT == 2) {
                float2 xx = *(const float2*)(x + (size_t)s * C + c0);
                xv[0] = xx.x; xv[1] = xx.y;
            } else {
                xv[0] = x[(size_t)s * C + c0];
            }
            #pragma unroll
            for (int c = 0; c < CPT; c++) {
                ull d2 = pack2(ebr[c], 0.f);
                #pragma unroll
                for (int j = 0; j < KP; j++) d2 = ffma2(wreg[c][j], eap[j], d2);
                float2 p = unpack2(d2);
                acc[c] += fmaxf(xv[c] + p.x + p.y, 0.f);
            }
        }
    }

    if (CPT == 2) {
        float2 xx = *(const float2*)(x + (size_t)node * C + c0);
        *(float2*)(g_u + (size_t)node * C + c0) =
            make_float2(xx.x + acc[0], xx.y + acc[1]);
    } else {
        g_u[(size_t)node * C + c0] = x[(size_t)node * C + c0] + acc[0];
    }
}

// ---------------- node update: h2 = relu(relu(u W1^T + b1) W2^T + b2) ------
// 128-node tile, 256 threads. Warp w owns output channels [w*8, w*8+8);
// each lane handles nodes {lane, lane+32, lane+64, lane+96}. Weight LDS are
// warp-broadcast; u LDS conflict-free. BN partial stats via shfl reduce.
template <int CIN>
__global__ void __launch_bounds__(256, 2) node_kernel(
    const float* __restrict__ w1, const float* __restrict__ b1,
    const float* __restrict__ w2, const float* __restrict__ b2)
{
    constexpr int KP1 = CIN / 2;   // 16 or 32
    constexpr int US  = KP1 + 1;
    constexpr int KP2 = cH / 2;    // 32
    constexpr int HS  = KP2 + 1;   // 33
    constexpr int WS  = KP2 + 1;   // padded weight stride (covers both)

    extern __shared__ __align__(16) ull dyn[];
    ull* us2 = dyn;                    // [128 * US]
    ull* ws2 = us2 + 128 * US;         // [64 * WS]
    ull* hs2 = ws2 + 64 * WS;          // [128 * HS]
    float* hsf = (float*)hs2;

    int t = threadIdx.x;
    int lane = t & 31;
    int w = t >> 5;                    // warp id = output group
    int n0 = blockIdx.x * 128;

    // load u tile (zero-pad invalid nodes)
    for (int i = t; i < 128 * KP1; i += 256) {
        int n = i / KP1, j = i % KP1;
        us2[n * US + j] = (n0 + n < cN)
            ? *(const ull*)&g_u[(size_t)(n0 + n) * CIN + 2 * j] : 0ull;
    }
    for (int i = t; i < cH * KP1; i += 256) {
        int r = i / KP1, j = i % KP1;
        ws2[r * WS + j] = ((const ull*)w1)[i];
    }
    __syncthreads();

    // ---- GEMM 1 ----
    ull acc2[4][8];
    #pragma unroll
    for (int j = 0; j < 8; j++) {
        ull b = pack2(b1[w * 8 + j], 0.f);
        #pragma unroll
        for (int i = 0; i < 4; i++) acc2[i][j] = b;
    }
    for (int kp = 0; kp < KP1; kp++) {
        ull wt[8], uv[4];
        #pragma unroll
        for (int j = 0; j < 8; j++) wt[j] = ws2[(w * 8 + j) * WS + kp];
        #pragma unroll
        for (int i = 0; i < 4; i++) uv[i] = us2[(lane + 32 * i) * US + kp];
        #pragma unroll
        for (int i = 0; i < 4; i++)
            #pragma unroll
            for (int j = 0; j < 8; j++)
                acc2[i][j] = ffma2(wt[j], uv[i], acc2[i][j]);
    }
    #pragma unroll
    for (int i = 0; i < 4; i++) {
        int n = lane + 32 * i;
        #pragma unroll
        for (int j = 0; j < 8; j += 2) {
            float2 pa = unpack2(acc2[i][j]);
            float2 pb = unpack2(acc2[i][j + 1]);
            ull pk = pack2(fmaxf(pa.x + pa.y, 0.f), fmaxf(pb.x + pb.y, 0.f));
            *(ull*)&hsf[n * (2 * HS) + w * 8 + j] = pk;
        }
    }
    __syncthreads();

    for (int i = t; i < cH * KP2; i += 256) {
        int r = i / KP2, j = i % KP2;
        ws2[r * WS + j] = ((const ull*)w2)[i];
    }
    __syncthreads();

    // ---- GEMM 2 ----
    #pragma unroll
    for (int j = 0; j < 8; j++) {
        ull b = pack2(b2[w * 8 + j], 0.f);
        #pragma unroll
        for (int i = 0; i < 4; i++) acc2[i][j] = b;
    }
    for (int kp = 0; kp < KP2; kp++) {
        ull wt[8], uv[4];
        #pragma unroll
        for (int j = 0; j < 8; j++) wt[j] = ws2[(w * 8 + j) * WS + kp];
        #pragma unroll
        for (int i = 0; i < 4; i++) uv[i] = hs2[(lane + 32 * i) * HS + kp];
        #pragma unroll
        for (int i = 0; i < 4; i++)
            #pragma unroll
            for (int j = 0; j < 8; j++)
                acc2[i][j] = ffma2(wt[j], uv[i], acc2[i][j]);
    }

    float v[4][8];
    float s[8], q[8];
    #pragma unroll
    for (int j = 0; j < 8; j++) { s[j] = 0.f; q[j] = 0.f; }
    #pragma unroll
    for (int i = 0; i < 4; i++) {
        bool valid = (n0 + lane + 32 * i) < cN;
        #pragma unroll
        for (int j = 0; j < 8; j++) {
            float2 p = unpack2(acc2[i][j]);
            float vv = valid ? fmaxf(p.x + p.y, 0.f) : 0.f;
            v[i][j] = vv;
            s[j] += vv; q[j] += vv * vv;
        }
    }
    // BN partial sums: butterfly reduce within warp, lane 0 atomics
    #pragma unroll
    for (int j = 0; j < 8; j++) {
        #pragma unroll
        for (int off = 16; off > 0; off >>= 1) {
            s[j] += __shfl_xor_sync(0xffffffffu, s[j], off);
            q[j] += __shfl_xor_sync(0xffffffffu, q[j], off);
        }
    }
    if (lane == 0) {
        #pragma unroll
        for (int j = 0; j < 8; j++) {
            atomicAdd(&g_sum[w * 8 + j], s[j]);
            atomicAdd(&g_sumsq[w * 8 + j], q[j]);
        }
    }

    __syncthreads();  // all hs2 reads complete; reuse for h2 staging
    #pragma unroll
    for (int i = 0; i < 4; i++) {
        int n = lane + 32 * i;
        #pragma unroll
        for (int j = 0; j < 8; j += 2) {
            ull pk = pack2(v[i][j], v[i][j + 1]);
            *(ull*)&hsf[n * (2 * HS) + w * 8 + j] = pk;
        }
    }
    __syncthreads();
    // coalesced store of h2
    for (int i = t; i < 128 * cH / 2; i += 256) {
        int n = i / KP2, j = i % KP2;
        if (n0 + n < cN)
            *(ull*)&g_h[(size_t)(n0 + n) * cH + 2 * j] = *(ull*)&hsf[n * (2 * HS) + 2 * j];
    }
}

// ---------------- BN normalize (+ relu), optionally fused graph pooling ----
__global__ void __launch_bounds__(256) norm_kernel(
    const float* __restrict__ gamma, const float* __restrict__ beta,
    const int* __restrict__ batch, int last)
{
    int idx = blockIdx.x * 256 + threadIdx.x;
    if (idx >= cN * 16) return;
    int node = idx >> 4;
    int c0 = (idx & 15) * 4;
    float4 h = ((const float4*)g_h)[idx];
    float v[4] = {h.x, h.y, h.z, h.w};
    #pragma unroll
    for (int j = 0; j < 4; j++) {
        int c = c0 + j;
        float mu  = g_sum[c]   * (1.f / cN);
        float var = g_sumsq[c] * (1.f / cN) - mu * mu;
        float sc  = rsqrtf(var + 1e-5f) * gamma[c];
        v[j] = fmaxf((v[j] - mu) * sc + beta[c], 0.f);
    }
    ((float4*)g_x)[idx] = make_float4(v[0], v[1], v[2], v[3]);
    if (last) {
        int b = batch[node];
        red_add_v4(&g_pool[b * cH + c0], v[0], v[1], v[2], v[3]);
        if (c0 == 0) atomicAdd(&g_cnt[b], 1);
    }
}

// ---------------- pooled mean + MLP head -----------------------------------
__global__ void __launch_bounds__(128) head_kernel(
    const float* __restrict__ hw1, const float* __restrict__ hb1,
    const float* __restrict__ hw2, const float* __restrict__ hb2,
    float* __restrict__ out)
{
    __shared__ float p[cH], z[cMH];
    int g = blockIdx.x, t = threadIdx.x;
    if (t < cH) p[t] = g_pool[g * cH + t] / fmaxf((float)g_cnt[g], 1.f);
    __syncthreads();
    float acc = hb1[t];
    for (int c = 0; c < cH; c++) acc += p[c] * hw1[t * cH + c];
    z[t] = fmaxf(acc, 0.f);
    __syncthreads();
    if (t < cOUT) {
        float a = hb2[t];
        for (int m = 0; m < cMH; m++) a += z[m] * hw2[t * cMH + m];
        out[g * cOUT + t] = a;
    }
}

// ---------------- launch ----------------------------------------------------
extern "C" void kernel_launch(void* const* d_in, const int* in_sizes, int n_in,
                              void* d_out, int out_size)
{
    const float* x    = (const float*)d_in[0];
    const int*   ei   = (const int*)  d_in[1];
    const float* ea   = (const float*)d_in[2];
    const int*   batch= (const int*)  d_in[3];
    const float* l0ew = (const float*)d_in[4];
    const float* l0eb = (const float*)d_in[5];
    const float* l0w1 = (const float*)d_in[6];
    const float* l0b1 = (const float*)d_in[7];
    const float* l0w2 = (const float*)d_in[8];
    const float* l0b2 = (const float*)d_in[9];
    const float* ewA  = (const float*)d_in[10];  // [3, H, DE]
    const float* ebA  = (const float*)d_in[11];  // [3, H]
    const float* w1A  = (const float*)d_in[12];  // [3, H, H]
    const float* b1A  = (const float*)d_in[13];
    const float* w2A  = (const float*)d_in[14];
    const float* b2A  = (const float*)d_in[15];
    const float* bng  = (const float*)d_in[16];  // [4, H]
    const float* bnb  = (const float*)d_in[17];
    const float* hw1  = (const float*)d_in[18];
    const float* hb1  = (const float*)d_in[19];
    const float* hw2  = (const float*)d_in[20];
    const float* hb2  = (const float*)d_in[21];
    float* out = (float*)d_out;

    const int EB = (cE + 255) / 256;       // 6250
    const int GB = cN / 8;                 // 12500
    const int NB = (cN + 127) / 128;       // 782
    const int MB = cN * 16 / 256;          // 6250
    const int IB = (cN + 255) / 256;

    // dynamic smem sizes for node kernels
    const int SM32 = (128 * (cDIN / 2 + 1) + cH * 33 + 128 * 33) * 8;
    const int SM64 = (128 * (cH   / 2 + 1) + cH * 33 + 128 * 33) * 8;
    cudaFuncSetAttribute(node_kernel<cDIN>,
                         cudaFuncAttributeMaxDynamicSharedMemorySize, SM32);
    cudaFuncSetAttribute(node_kernel<cH>,
                         cudaFuncAttributeMaxDynamicSharedMemorySize, SM64);

    // CSR build (by dst) + edge_attr permutation
    init_kernel<<<IB, 256>>>();
    hist_kernel<<<EB, 256>>>(ei);
    scan_kernel<<<1, 1024>>>();
    scatter_kernel<<<EB, 256>>>(ei, ea);

    // layer 0 (CIN = 32)
    gather_kernel<cDIN><<<GB, 256>>>(x, 0, l0ew, l0eb);
    node_kernel<cDIN><<<NB, 256, SM32>>>(l0w1, l0b1, l0w2, l0b2);
    norm_kernel<<<MB, 256>>>(bng, bnb, batch, 0);

    // layers 1..3 (CIN = 64)
    for (int i = 0; i < 3; i++) {
        int last = (i == 2) ? 1 : 0;
        gather_kernel<cH><<<GB, 256>>>(nullptr, 1,
                                       ewA + (size_t)i * cH * cDE, ebA + (size_t)i * cH);
        node_kernel<cH><<<NB, 256, SM64>>>(w1A + (size_t)i * cH * cH, b1A + (size_t)i * cH,
                                           w2A + (size_t)i * cH * cH, b2A + (size_t)i * cH);
        norm_kernel<<<MB, 256>>>(bng + (size_t)(i + 1) * cH,
                                 bnb + (size_t)(i + 1) * cH, batch, last);
    }

    head_kernel<<<cG, 128>>>(hw1, hb1, hw2, hb2, out);
}